// round 14
// baseline (speedup 1.0000x reference)
#include <cuda_runtime.h>
#include <cuda_fp16.h>

// ---------------- problem constants ----------------
#define NN    50000
#define EE    800000
#define ET    (EE + NN)      // edges + self loops = 850000
#define HC    256            // HEADS * 64
#define CC    64
#define NEG   0.2f
#define SPLIT 37632          // pipeline split point (multiple of 128)
#define MAXD  128            // slots per destination

typedef unsigned long long ull;

// ---------------- device scratch (static, no allocs) ----------------
__device__ __half g_hh [(size_t)NN * HC];      // hidden, fp16, [N,256]
__device__ float  g_as [NN * 4];               // alpha_src [N,H]
__device__ float  g_ad [NN * 4];               // alpha_dst [N,H]
__device__ float  g_x2 [(size_t)NN * CC];      // layer1 output (fp32)
__device__ int    g_srcs[(size_t)NN * MAXD];   // slotted CSR: src per edge
__device__ int    g_cnt[NN];                   // zero at entry; re-zeroed by agg<0>
__device__ int    g_is64;

// ---------------- helpers ----------------
__device__ __forceinline__ void ffma2(ull& acc, ull a, ull b) {
    asm("fma.rn.f32x2 %0, %1, %2, %0;" : "+l"(acc) : "l"(a), "l"(b));
}
__device__ __forceinline__ ull pack2(float x, float y) {
    ull r;
    asm("mov.b64 %0, {%1, %2};" : "=l"(r) : "f"(x), "f"(y));
    return r;
}
__device__ __forceinline__ void unpack2(ull v, float& x, float& y) {
    asm("mov.b64 {%0, %1}, %2;" : "=f"(x), "=f"(y) : "l"(v));
}
__device__ __forceinline__ ull f2u(float2 v) { return pack2(v.x, v.y); }

// ---------------- dtype detection ----------------
__global__ void detect_idx_kernel(const int* __restrict__ words) {
    __shared__ int any;
    if (threadIdx.x == 0) any = 0;
    __syncthreads();
    for (int j = threadIdx.x; j < 1024; j += blockDim.x)
        if (words[2 * j + 1] != 0) any = 1;
    __syncthreads();
    if (threadIdx.x == 0) g_is64 = any ? 0 : 1;
}

// ---------------- one-pass slotted CSR fill ----------------
__global__ void fill_kernel(const void* __restrict__ ei) {
    int e = blockIdx.x * blockDim.x + threadIdx.x;
    if (e >= ET) return;
    int s, d;
    if (e < EE) {
        if (g_is64) {
            const long long* p = (const long long*)ei;
            s = (int)p[e]; d = (int)p[EE + e];
        } else {
            const int* p = (const int*)ei;
            s = p[e]; d = p[EE + e];
        }
    } else {
        s = d = e - EE;   // self loop
    }
    int pos = atomicAdd(&g_cnt[d], 1);
    if (pos < MAXD) g_srcs[(size_t)d * MAXD + pos] = s;
}

// ---------------- tensor-core GEMM (fp16 mma.sync, fp32 accum) ------------
__device__ __forceinline__ unsigned smem_u32(const void* p) {
    return (unsigned)__cvta_generic_to_shared(p);
}
__device__ __forceinline__ void ldmatrix_x4(unsigned& r0, unsigned& r1,
                                            unsigned& r2, unsigned& r3, unsigned addr) {
    asm volatile("ldmatrix.sync.aligned.m8n8.x4.shared.b16 {%0,%1,%2,%3}, [%4];"
                 : "=r"(r0), "=r"(r1), "=r"(r2), "=r"(r3) : "r"(addr));
}
__device__ __forceinline__ void ldmatrix_x2(unsigned& r0, unsigned& r1, unsigned addr) {
    asm volatile("ldmatrix.sync.aligned.m8n8.x2.shared.b16 {%0,%1}, [%2];"
                 : "=r"(r0), "=r"(r1) : "r"(addr));
}
__device__ __forceinline__ void mma16816(float* d, const unsigned* a, const unsigned* b) {
    asm volatile("mma.sync.aligned.m16n8k16.row.col.f32.f16.f16.f32 "
                 "{%0,%1,%2,%3}, {%4,%5,%6,%7}, {%8,%9}, {%0,%1,%2,%3};"
                 : "+f"(d[0]), "+f"(d[1]), "+f"(d[2]), "+f"(d[3])
                 : "r"(a[0]), "r"(a[1]), "r"(a[2]), "r"(a[3]), "r"(b[0]), "r"(b[1]));
}

#define ASTRIDE 40   // halfs per row; 80B row stride -> conflict-free ldmatrix

template <int K>
__global__ void __launch_bounds__(256)
gemm_tc_kernel(const float* __restrict__ X, const float* __restrict__ W,
               const float* __restrict__ a_src, const float* __restrict__ a_dst,
               int row0) {
    __shared__ __align__(16) __half As[128 * ASTRIDE];
    __shared__ __align__(16) __half Bs[64 * ASTRIDE];
    __shared__ float sred[2][128];
    __shared__ float dred[2][128];

    int tid = threadIdx.x;
    int lane = tid & 31, wid = tid >> 5;
    int wm = wid >> 1, wn = wid & 1;
    int bm = row0 + blockIdx.x * 128;
    int head = blockIdx.y;
    int bn = head * 64;

    float d[2][4][4];
    #pragma unroll
    for (int mt = 0; mt < 2; mt++)
        #pragma unroll
        for (int nt = 0; nt < 4; nt++)
            #pragma unroll
            for (int j = 0; j < 4; j++) d[mt][nt][j] = 0.f;

    for (int kt = 0; kt < K; kt += 32) {
        #pragma unroll
        for (int i = 0; i < 8; i++) {
            int lin = tid + i * 256;
            int r = lin >> 4, c2 = lin & 15;
            int row = bm + r;
            float2 v = make_float2(0.f, 0.f);
            if (row < NN) v = *(const float2*)&X[(size_t)row * K + kt + c2 * 2];
            *(__half2*)&As[r * ASTRIDE + c2 * 2] = __floats2half2_rn(v.x, v.y);
        }
        #pragma unroll
        for (int i = 0; i < 4; i++) {
            int lin = tid + i * 256;
            int r = lin >> 4, c2 = lin & 15;
            float2 v = *(const float2*)&W[(size_t)(bn + r) * K + kt + c2 * 2];
            *(__half2*)&Bs[r * ASTRIDE + c2 * 2] = __floats2half2_rn(v.x, v.y);
        }
        __syncthreads();

        #pragma unroll
        for (int kk = 0; kk < 32; kk += 16) {
            unsigned a[2][4], b[4][2];
            int l15 = lane & 15, lh = lane >> 4;
            #pragma unroll
            for (int mt = 0; mt < 2; mt++) {
                unsigned addr = smem_u32(&As[(wm * 32 + mt * 16 + l15) * ASTRIDE + kk + lh * 8]);
                ldmatrix_x4(a[mt][0], a[mt][1], a[mt][2], a[mt][3], addr);
            }
            int l7 = lane & 7, kh = (lane >> 3) & 1;
            #pragma unroll
            for (int nt = 0; nt < 4; nt++) {
                unsigned addr = smem_u32(&Bs[(wn * 32 + nt * 8 + l7) * ASTRIDE + kk + kh * 8]);
                ldmatrix_x2(b[nt][0], b[nt][1], addr);
            }
            #pragma unroll
            for (int mt = 0; mt < 2; mt++)
                #pragma unroll
                for (int nt = 0; nt < 4; nt++)
                    mma16816(d[mt][nt], a[mt], b[nt]);
        }
        __syncthreads();
    }

    // ---- epilogue: fp16 store + alpha partials ----
    int qrow = lane >> 2;
    int qcol = (lane & 3) * 2;
    float2 av[4], dv[4];
    #pragma unroll
    for (int nt = 0; nt < 4; nt++) {
        int c = wn * 32 + nt * 8 + qcol;
        av[nt] = *(const float2*)&a_src[bn + c];
        dv[nt] = *(const float2*)&a_dst[bn + c];
    }

    float sp[2][2] = {}, dp[2][2] = {};
    #pragma unroll
    for (int mt = 0; mt < 2; mt++) {
        int row = bm + wm * 32 + mt * 16 + qrow;
        #pragma unroll
        for (int nt = 0; nt < 4; nt++) {
            float d0 = d[mt][nt][0], d1 = d[mt][nt][1];
            float d2 = d[mt][nt][2], d3 = d[mt][nt][3];
            int col = bn + wn * 32 + nt * 8 + qcol;
            if (row < NN) {
                __half2 h = __floats2half2_rn(d0, d1);
                *(unsigned*)&g_hh[(size_t)row * HC + col] = *(unsigned*)&h;
            }
            if (row + 8 < NN) {
                __half2 h = __floats2half2_rn(d2, d3);
                *(unsigned*)&g_hh[(size_t)(row + 8) * HC + col] = *(unsigned*)&h;
            }
            sp[mt][0] += d0 * av[nt].x + d1 * av[nt].y;
            sp[mt][1] += d2 * av[nt].x + d3 * av[nt].y;
            dp[mt][0] += d0 * dv[nt].x + d1 * dv[nt].y;
            dp[mt][1] += d2 * dv[nt].x + d3 * dv[nt].y;
        }
    }
    #pragma unroll
    for (int mt = 0; mt < 2; mt++)
        #pragma unroll
        for (int h = 0; h < 2; h++) {
            sp[mt][h] += __shfl_xor_sync(0xFFFFFFFFu, sp[mt][h], 1);
            sp[mt][h] += __shfl_xor_sync(0xFFFFFFFFu, sp[mt][h], 2);
            dp[mt][h] += __shfl_xor_sync(0xFFFFFFFFu, dp[mt][h], 1);
            dp[mt][h] += __shfl_xor_sync(0xFFFFFFFFu, dp[mt][h], 2);
        }
    if ((lane & 3) == 0) {
        #pragma unroll
        for (int mt = 0; mt < 2; mt++) {
            int rl = wm * 32 + mt * 16 + qrow;
            sred[wn][rl]     = sp[mt][0];
            sred[wn][rl + 8] = sp[mt][1];
            dred[wn][rl]     = dp[mt][0];
            dred[wn][rl + 8] = dp[mt][1];
        }
    }
    __syncthreads();
    if (tid < 128) {
        int row = bm + tid;
        if (row < NN) {
            g_as[row * 4 + head] = sred[0][tid] + sred[1][tid];
            g_ad[row * 4 + head] = dred[0][tid] + dred[1][tid];
        }
    }
}

// ------- single-pass softmax + aggregate, f32x2 packed accumulation -------
// lane L: head = L>>3, cols = (L&7)*8-block of that head's 64.
template <int ACT>
__global__ void __launch_bounds__(256, 5)
aggregate_kernel(float* __restrict__ out, const float* __restrict__ bias,
                 int dd0, int nd) {
    int d = dd0 + ((blockIdx.x * blockDim.x + threadIdx.x) >> 5);
    int lane = threadIdx.x & 31;
    if (d >= dd0 + nd) return;
    int cnt = g_cnt[d];
    if (!ACT && lane == 0) g_cnt[d] = 0;   // recycle counters for next call
    if (cnt > MAXD) cnt = MAXD;
    int beg = d * MAXD, end = beg + cnt;
    int hsel = lane >> 3;
    float adh = g_ad[d * 4 + hsel];

    float den = 0.f;
    ull a01 = 0ull, a23 = 0ull, a45 = 0ull, a67 = 0ull;

    int i = beg;
    for (; i + 3 < end; i += 4) {
        int   s[4];
        float a[4];
        uint4 u[4];
        #pragma unroll
        for (int j = 0; j < 4; j++) s[j] = g_srcs[i + j];
        #pragma unroll
        for (int j = 0; j < 4; j++) a[j] = g_as[s[j] * 4 + hsel];
        #pragma unroll
        for (int j = 0; j < 4; j++)
            u[j] = ((const uint4*)(g_hh + (size_t)s[j] * HC))[lane];
        #pragma unroll
        for (int j = 0; j < 4; j++) {
            float e = a[j] + adh; e = e > 0.f ? e : NEG * e;
            float ex = __expf(e);
            den += ex;
            ull exd = pack2(ex, ex);
            ffma2(a01, f2u(__half22float2(*(const __half2*)&u[j].x)), exd);
            ffma2(a23, f2u(__half22float2(*(const __half2*)&u[j].y)), exd);
            ffma2(a45, f2u(__half22float2(*(const __half2*)&u[j].z)), exd);
            ffma2(a67, f2u(__half22float2(*(const __half2*)&u[j].w)), exd);
        }
    }
    for (; i < end; i++) {
        int s0 = g_srcs[i];
        float af = g_as[s0 * 4 + hsel];
        uint4 u0 = ((const uint4*)(g_hh + (size_t)s0 * HC))[lane];
        float e = af + adh; e = e > 0.f ? e : NEG * e;
        float ex = __expf(e);
        den += ex;
        ull exd = pack2(ex, ex);
        ffma2(a01, f2u(__half22float2(*(const __half2*)&u0.x)), exd);
        ffma2(a23, f2u(__half22float2(*(const __half2*)&u0.y)), exd);
        ffma2(a45, f2u(__half22float2(*(const __half2*)&u0.z)), exd);
        ffma2(a67, f2u(__half22float2(*(const __half2*)&u0.w)), exd);
    }

    float acc[8];
    unpack2(a01, acc[0], acc[1]);
    unpack2(a23, acc[2], acc[3]);
    unpack2(a45, acc[4], acc[5]);
    unpack2(a67, acc[6], acc[7]);

    // normalize, then head-sum (lanes with same lane&7 hold the 4 heads)
    float wnorm = 0.25f / (den + 1e-16f);
    #pragma unroll
    for (int k = 0; k < 8; k++) {
        acc[k] *= wnorm;
        acc[k] += __shfl_xor_sync(0xFFFFFFFFu, acc[k], 8);
        acc[k] += __shfl_xor_sync(0xFFFFFFFFu, acc[k], 16);
    }

    if (lane < 8) {
        float4 b0 = *(const float4*)(bias + lane * 8);
        float4 b1 = *(const float4*)(bias + lane * 8 + 4);
        float4 r0, r1;
        r0.x = acc[0] + b0.x; r0.y = acc[1] + b0.y;
        r0.z = acc[2] + b0.z; r0.w = acc[3] + b0.w;
        r1.x = acc[4] + b1.x; r1.y = acc[5] + b1.y;
        r1.z = acc[6] + b1.z; r1.w = acc[7] + b1.w;
        if (ACT) {
            r0.x = r0.x > 0.f ? r0.x : expm1f(r0.x);
            r0.y = r0.y > 0.f ? r0.y : expm1f(r0.y);
            r0.z = r0.z > 0.f ? r0.z : expm1f(r0.z);
            r0.w = r0.w > 0.f ? r0.w : expm1f(r0.w);
            r1.x = r1.x > 0.f ? r1.x : expm1f(r1.x);
            r1.y = r1.y > 0.f ? r1.y : expm1f(r1.y);
            r1.z = r1.z > 0.f ? r1.z : expm1f(r1.z);
            r1.w = r1.w > 0.f ? r1.w : expm1f(r1.w);
        }
        *(float4*)(out + (size_t)d * CC + lane * 8)     = r0;
        *(float4*)(out + (size_t)d * CC + lane * 8 + 4) = r1;
    }
}

// ---------------- host launch ----------------
extern "C" void kernel_launch(void* const* d_in, const int* in_sizes, int n_in,
                              void* d_out, int out_size) {
    const float* x      = (const float*)d_in[0];
    const void*  ei     = d_in[1];
    const float* W1     = (const float*)d_in[2];
    const float* a_src1 = (const float*)d_in[3];
    const float* a_dst1 = (const float*)d_in[4];
    const float* b1     = (const float*)d_in[5];
    const float* W2     = (const float*)d_in[6];
    const float* a_src2 = (const float*)d_in[7];
    const float* a_dst2 = (const float*)d_in[8];
    const float* b2     = (const float*)d_in[9];
    float* out = (float*)d_out;

    void* p_x2;
    cudaGetSymbolAddress(&p_x2, g_x2);
    float* x2 = (float*)p_x2;

    static cudaStream_t s2 = []{
        cudaStream_t t; cudaStreamCreateWithFlags(&t, cudaStreamNonBlocking); return t;
    }();
    static cudaEvent_t ev_fork = []{
        cudaEvent_t e; cudaEventCreateWithFlags(&e, cudaEventDisableTiming); return e;
    }();
    static cudaEvent_t ev_join = []{
        cudaEvent_t e; cudaEventCreateWithFlags(&e, cudaEventDisableTiming); return e;
    }();
    static cudaEvent_t ev_a0 = []{
        cudaEvent_t e; cudaEventCreateWithFlags(&e, cudaEventDisableTiming); return e;
    }();
    static cudaEvent_t ev_g0 = []{
        cudaEvent_t e; cudaEventCreateWithFlags(&e, cudaEventDisableTiming); return e;
    }();

    const int TB = 256;
    dim3 gemm_full((NN + 127) / 128, 4);
    dim3 gemm_h0(SPLIT / 128, 4);
    dim3 gemm_h1((NN - SPLIT + 127) / 128, 4);
    int agg_h0 = (SPLIT * 32) / TB;
    int agg_h1 = ((NN - SPLIT) * 32 + TB - 1) / TB;
    int agg_full = (NN * 32 + TB - 1) / TB;
    int edge_blocks = (ET + TB - 1) / TB;

    // -------- fork: slotted CSR on side stream, GEMM1 on main --------
    cudaEventRecord(ev_fork, 0);
    cudaStreamWaitEvent(s2, ev_fork, 0);

    detect_idx_kernel<<<1, 256, 0, s2>>>((const int*)ei);
    fill_kernel<<<edge_blocks, TB, 0, s2>>>(ei);
    cudaEventRecord(ev_join, s2);

    gemm_tc_kernel<128><<<gemm_full, TB>>>(x, W1, a_src1, a_dst1, 0);

    // -------- join; pipelined agg1 / GEMM2 --------
    cudaStreamWaitEvent(0, ev_join, 0);
    aggregate_kernel<1><<<agg_h0, TB>>>(x2, b1, 0, SPLIT);
    cudaEventRecord(ev_a0, 0);
    cudaStreamWaitEvent(s2, ev_a0, 0);
    gemm_tc_kernel<64><<<gemm_h0, TB, 0, s2>>>(x2, W2, a_src2, a_dst2, 0);
    cudaEventRecord(ev_g0, s2);

    aggregate_kernel<1><<<agg_h1, TB>>>(x2, b1, SPLIT, NN - SPLIT);
    gemm_tc_kernel<64><<<gemm_h1, TB>>>(x2, W2, a_src2, a_dst2, SPLIT);

    // -------- final aggregate (needs both GEMM2 halves) --------
    cudaStreamWaitEvent(0, ev_g0, 0);
    aggregate_kernel<0><<<agg_full, TB>>>(out, b2, 0, NN);
}

// round 15
// speedup vs baseline: 1.9041x; 1.9041x over previous
#include <cuda_runtime.h>
#include <cuda_fp16.h>

// ---------------- problem constants ----------------
#define NN    50000
#define EE    800000
#define ET    (EE + NN)      // edges + self loops = 850000
#define HC    256            // HEADS * 64
#define CC    64
#define NEG   0.2f
#define LOG2E 1.4426950408889634f
#define SPLIT 37632          // pipeline split point (multiple of 128)

typedef unsigned long long ull;

// ---------------- device scratch (static, no allocs) ----------------
__device__ __half g_hh [(size_t)NN * HC];  // hidden, fp16, [N,256]
__device__ float  g_as [NN * 4];           // alpha_src * log2e  [N,H]
__device__ float  g_ad [NN * 4];           // alpha_dst * log2e  [N,H]
__device__ float  g_x2 [(size_t)NN * CC];  // layer1 output (fp32)
__device__ int    g_srcs[ET];              // packed CSR: src per edge
__device__ int    g_cnt[NN];
__device__ int    g_cur[NN];               // preloaded with segment base
__device__ int2   g_offcnt[NN];            // (offset, count) per dst
__device__ int    g_total;
__device__ int    g_is64;

// ---------------- helpers ----------------
__device__ __forceinline__ void ffma2(ull& acc, ull a, ull b) {
    asm("fma.rn.f32x2 %0, %1, %2, %0;" : "+l"(acc) : "l"(a), "l"(b));
}
__device__ __forceinline__ ull pack2(float x, float y) {
    ull r;
    asm("mov.b64 %0, {%1, %2};" : "=l"(r) : "f"(x), "f"(y));
    return r;
}
__device__ __forceinline__ void unpack2(ull v, float& x, float& y) {
    asm("mov.b64 {%0, %1}, %2;" : "=f"(x), "=f"(y) : "l"(v));
}
__device__ __forceinline__ ull f2u(float2 v) { return pack2(v.x, v.y); }
__device__ __forceinline__ float ex2f(float x) {
    float r;
    asm("ex2.approx.f32 %0, %1;" : "=f"(r) : "f"(x));
    return r;
}

__device__ __forceinline__ void edge_sd(const void* ei, int e, int& s, int& d) {
    if (e < EE) {
        if (g_is64) {
            const long long* p = (const long long*)ei;
            s = (int)p[e]; d = (int)p[EE + e];
        } else {
            const int* p = (const int*)ei;
            s = p[e]; d = p[EE + e];
        }
    } else {
        s = d = e - EE;   // self loop
    }
}

// ---------------- fused init: zero counters + dtype detection ----------------
__global__ void init_kernel(const int* __restrict__ words) {
    int i = blockIdx.x * blockDim.x + threadIdx.x;
    if (i < NN) g_cnt[i] = 0;
    if (blockIdx.x == 0) {
        __shared__ int any;
        if (threadIdx.x == 0) { any = 0; g_total = 0; }
        __syncthreads();
        for (int j = threadIdx.x; j < 1024; j += blockDim.x)
            if (words[2 * j + 1] != 0) any = 1;
        __syncthreads();
        if (threadIdx.x == 0) g_is64 = any ? 0 : 1;
    }
}

// ---------------- CSR build (packed, order-free segments) ----------------
__global__ void hist_kernel(const void* __restrict__ ei) {
    int e = blockIdx.x * blockDim.x + threadIdx.x;
    if (e >= ET) return;
    int d;
    if (e < EE) {
        d = g_is64 ? ((const int*)ei)[2 * (EE + e)] : ((const int*)ei)[EE + e];
    } else {
        d = e - EE;
    }
    atomicAdd(&g_cnt[d], 1);
}

__global__ void assign_offsets_kernel() {
    int i = blockIdx.x * blockDim.x + threadIdx.x;
    if (i >= NN) return;
    int c = g_cnt[i];
    int o = atomicAdd(&g_total, c);
    g_offcnt[i] = make_int2(o, c);
    g_cur[i] = o;                 // fill's atomic starts at the segment base
}

__global__ void fill_kernel(const void* __restrict__ ei) {
    int e = blockIdx.x * blockDim.x + threadIdx.x;
    if (e >= ET) return;
    int s, d; edge_sd(ei, e, s, d);
    int pos = atomicAdd(&g_cur[d], 1);
    g_srcs[pos] = s;
}

// ---------------- tensor-core GEMM (fp16 mma.sync, fp32 accum) ------------
__device__ __forceinline__ unsigned smem_u32(const void* p) {
    return (unsigned)__cvta_generic_to_shared(p);
}
__device__ __forceinline__ void ldmatrix_x4(unsigned& r0, unsigned& r1,
                                            unsigned& r2, unsigned& r3, unsigned addr) {
    asm volatile("ldmatrix.sync.aligned.m8n8.x4.shared.b16 {%0,%1,%2,%3}, [%4];"
                 : "=r"(r0), "=r"(r1), "=r"(r2), "=r"(r3) : "r"(addr));
}
__device__ __forceinline__ void ldmatrix_x2(unsigned& r0, unsigned& r1, unsigned addr) {
    asm volatile("ldmatrix.sync.aligned.m8n8.x2.shared.b16 {%0,%1}, [%2];"
                 : "=r"(r0), "=r"(r1) : "r"(addr));
}
__device__ __forceinline__ void mma16816(float* d, const unsigned* a, const unsigned* b) {
    asm volatile("mma.sync.aligned.m16n8k16.row.col.f32.f16.f16.f32 "
                 "{%0,%1,%2,%3}, {%4,%5,%6,%7}, {%8,%9}, {%0,%1,%2,%3};"
                 : "+f"(d[0]), "+f"(d[1]), "+f"(d[2]), "+f"(d[3])
                 : "r"(a[0]), "r"(a[1]), "r"(a[2]), "r"(a[3]), "r"(b[0]), "r"(b[1]));
}

#define ASTRIDE 40   // halfs per row; 80B row stride -> conflict-free ldmatrix

template <int K>
__global__ void __launch_bounds__(256)
gemm_tc_kernel(const float* __restrict__ X, const float* __restrict__ W,
               const float* __restrict__ a_src, const float* __restrict__ a_dst,
               int row0) {
    __shared__ __align__(16) __half As[128 * ASTRIDE];
    __shared__ __align__(16) __half Bs[64 * ASTRIDE];
    __shared__ float sred[2][128];
    __shared__ float dred[2][128];

    int tid = threadIdx.x;
    int lane = tid & 31, wid = tid >> 5;
    int wm = wid >> 1, wn = wid & 1;
    int bm = row0 + blockIdx.x * 128;
    int head = blockIdx.y;
    int bn = head * 64;

    float d[2][4][4];
    #pragma unroll
    for (int mt = 0; mt < 2; mt++)
        #pragma unroll
        for (int nt = 0; nt < 4; nt++)
            #pragma unroll
            for (int j = 0; j < 4; j++) d[mt][nt][j] = 0.f;

    for (int kt = 0; kt < K; kt += 32) {
        #pragma unroll
        for (int i = 0; i < 8; i++) {
            int lin = tid + i * 256;
            int r = lin >> 4, c2 = lin & 15;
            int row = bm + r;
            float2 v = make_float2(0.f, 0.f);
            if (row < NN) v = *(const float2*)&X[(size_t)row * K + kt + c2 * 2];
            *(__half2*)&As[r * ASTRIDE + c2 * 2] = __floats2half2_rn(v.x, v.y);
        }
        #pragma unroll
        for (int i = 0; i < 4; i++) {
            int lin = tid + i * 256;
            int r = lin >> 4, c2 = lin & 15;
            float2 v = *(const float2*)&W[(size_t)(bn + r) * K + kt + c2 * 2];
            *(__half2*)&Bs[r * ASTRIDE + c2 * 2] = __floats2half2_rn(v.x, v.y);
        }
        __syncthreads();

        #pragma unroll
        for (int kk = 0; kk < 32; kk += 16) {
            unsigned a[2][4], b[4][2];
            int l15 = lane & 15, lh = lane >> 4;
            #pragma unroll
            for (int mt = 0; mt < 2; mt++) {
                unsigned addr = smem_u32(&As[(wm * 32 + mt * 16 + l15) * ASTRIDE + kk + lh * 8]);
                ldmatrix_x4(a[mt][0], a[mt][1], a[mt][2], a[mt][3], addr);
            }
            int l7 = lane & 7, kh = (lane >> 3) & 1;
            #pragma unroll
            for (int nt = 0; nt < 4; nt++) {
                unsigned addr = smem_u32(&Bs[(wn * 32 + nt * 8 + l7) * ASTRIDE + kk + kh * 8]);
                ldmatrix_x2(b[nt][0], b[nt][1], addr);
            }
            #pragma unroll
            for (int mt = 0; mt < 2; mt++)
                #pragma unroll
                for (int nt = 0; nt < 4; nt++)
                    mma16816(d[mt][nt], a[mt], b[nt]);
        }
        __syncthreads();
    }

    // ---- epilogue: fp16 store + alpha partials (pre-scaled by log2e) ----
    int qrow = lane >> 2;
    int qcol = (lane & 3) * 2;
    float2 av[4], dv[4];
    #pragma unroll
    for (int nt = 0; nt < 4; nt++) {
        int c = wn * 32 + nt * 8 + qcol;
        av[nt] = *(const float2*)&a_src[bn + c];
        dv[nt] = *(const float2*)&a_dst[bn + c];
    }

    float sp[2][2] = {}, dp[2][2] = {};
    #pragma unroll
    for (int mt = 0; mt < 2; mt++) {
        int row = bm + wm * 32 + mt * 16 + qrow;
        #pragma unroll
        for (int nt = 0; nt < 4; nt++) {
            float d0 = d[mt][nt][0], d1 = d[mt][nt][1];
            float d2 = d[mt][nt][2], d3 = d[mt][nt][3];
            int col = bn + wn * 32 + nt * 8 + qcol;
            if (row < NN) {
                __half2 h = __floats2half2_rn(d0, d1);
                *(unsigned*)&g_hh[(size_t)row * HC + col] = *(unsigned*)&h;
            }
            if (row + 8 < NN) {
                __half2 h = __floats2half2_rn(d2, d3);
                *(unsigned*)&g_hh[(size_t)(row + 8) * HC + col] = *(unsigned*)&h;
            }
            sp[mt][0] += d0 * av[nt].x + d1 * av[nt].y;
            sp[mt][1] += d2 * av[nt].x + d3 * av[nt].y;
            dp[mt][0] += d0 * dv[nt].x + d1 * dv[nt].y;
            dp[mt][1] += d2 * dv[nt].x + d3 * dv[nt].y;
        }
    }
    #pragma unroll
    for (int mt = 0; mt < 2; mt++)
        #pragma unroll
        for (int h = 0; h < 2; h++) {
            sp[mt][h] += __shfl_xor_sync(0xFFFFFFFFu, sp[mt][h], 1);
            sp[mt][h] += __shfl_xor_sync(0xFFFFFFFFu, sp[mt][h], 2);
            dp[mt][h] += __shfl_xor_sync(0xFFFFFFFFu, dp[mt][h], 1);
            dp[mt][h] += __shfl_xor_sync(0xFFFFFFFFu, dp[mt][h], 2);
        }
    if ((lane & 3) == 0) {
        #pragma unroll
        for (int mt = 0; mt < 2; mt++) {
            int rl = wm * 32 + mt * 16 + qrow;
            sred[wn][rl]     = sp[mt][0];
            sred[wn][rl + 8] = sp[mt][1];
            dred[wn][rl]     = dp[mt][0];
            dred[wn][rl + 8] = dp[mt][1];
        }
    }
    __syncthreads();
    if (tid < 128) {
        int row = bm + tid;
        if (row < NN) {
            g_as[row * 4 + head] = (sred[0][tid] + sred[1][tid]) * LOG2E;
            g_ad[row * 4 + head] = (dred[0][tid] + dred[1][tid]) * LOG2E;
        }
    }
}

// ------- single-pass softmax + aggregate, f32x2 packed accumulation -------
// lane L: head = L>>3, cols = (L&7)*8-block of that head's 64.
// alphas are pre-scaled by log2e; leaky = fmaxf(e, 0.2e); exp via ex2.
template <int ACT>
__global__ void __launch_bounds__(256, 5)
aggregate_kernel(float* __restrict__ out, const float* __restrict__ bias,
                 int dd0, int nd) {
    int d = dd0 + ((blockIdx.x * blockDim.x + threadIdx.x) >> 5);
    int lane = threadIdx.x & 31;
    if (d >= dd0 + nd) return;
    int2 oc = g_offcnt[d];
    int beg = oc.x, end = oc.x + oc.y;
    int hsel = lane >> 3;
    float adh = g_ad[d * 4 + hsel];

    float den = 0.f;
    ull a01 = 0ull, a23 = 0ull, a45 = 0ull, a67 = 0ull;

    int i = beg;
    for (; i + 3 < end; i += 4) {
        int   s[4];
        float a[4];
        uint4 u[4];
        #pragma unroll
        for (int j = 0; j < 4; j++) s[j] = g_srcs[i + j];
        #pragma unroll
        for (int j = 0; j < 4; j++) a[j] = g_as[s[j] * 4 + hsel];
        #pragma unroll
        for (int j = 0; j < 4; j++)
            u[j] = ((const uint4*)(g_hh + (size_t)s[j] * HC))[lane];
        #pragma unroll
        for (int j = 0; j < 4; j++) {
            float e = a[j] + adh;
            float ex = ex2f(fmaxf(e, NEG * e));
            den += ex;
            ull exd = pack2(ex, ex);
            ffma2(a01, f2u(__half22float2(*(const __half2*)&u[j].x)), exd);
            ffma2(a23, f2u(__half22float2(*(const __half2*)&u[j].y)), exd);
            ffma2(a45, f2u(__half22float2(*(const __half2*)&u[j].z)), exd);
            ffma2(a67, f2u(__half22float2(*(const __half2*)&u[j].w)), exd);
        }
    }
    for (; i < end; i++) {
        int s0 = g_srcs[i];
        float af = g_as[s0 * 4 + hsel];
        uint4 u0 = ((const uint4*)(g_hh + (size_t)s0 * HC))[lane];
        float e = af + adh;
        float ex = ex2f(fmaxf(e, NEG * e));
        den += ex;
        ull exd = pack2(ex, ex);
        ffma2(a01, f2u(__half22float2(*(const __half2*)&u0.x)), exd);
        ffma2(a23, f2u(__half22float2(*(const __half2*)&u0.y)), exd);
        ffma2(a45, f2u(__half22float2(*(const __half2*)&u0.z)), exd);
        ffma2(a67, f2u(__half22float2(*(const __half2*)&u0.w)), exd);
    }

    float acc[8];
    unpack2(a01, acc[0], acc[1]);
    unpack2(a23, acc[2], acc[3]);
    unpack2(a45, acc[4], acc[5]);
    unpack2(a67, acc[6], acc[7]);

    // normalize, then head-sum (lanes with same lane&7 hold the 4 heads)
    float wnorm = 0.25f / (den + 1e-16f);
    #pragma unroll
    for (int k = 0; k < 8; k++) {
        acc[k] *= wnorm;
        acc[k] += __shfl_xor_sync(0xFFFFFFFFu, acc[k], 8);
        acc[k] += __shfl_xor_sync(0xFFFFFFFFu, acc[k], 16);
    }

    if (lane < 8) {
        float4 b0 = *(const float4*)(bias + lane * 8);
        float4 b1 = *(const float4*)(bias + lane * 8 + 4);
        float4 r0, r1;
        r0.x = acc[0] + b0.x; r0.y = acc[1] + b0.y;
        r0.z = acc[2] + b0.z; r0.w = acc[3] + b0.w;
        r1.x = acc[4] + b1.x; r1.y = acc[5] + b1.y;
        r1.z = acc[6] + b1.z; r1.w = acc[7] + b1.w;
        if (ACT) {
            r0.x = r0.x > 0.f ? r0.x : expm1f(r0.x);
            r0.y = r0.y > 0.f ? r0.y : expm1f(r0.y);
            r0.z = r0.z > 0.f ? r0.z : expm1f(r0.z);
            r0.w = r0.w > 0.f ? r0.w : expm1f(r0.w);
            r1.x = r1.x > 0.f ? r1.x : expm1f(r1.x);
            r1.y = r1.y > 0.f ? r1.y : expm1f(r1.y);
            r1.z = r1.z > 0.f ? r1.z : expm1f(r1.z);
            r1.w = r1.w > 0.f ? r1.w : expm1f(r1.w);
        }
        *(float4*)(out + (size_t)d * CC + lane * 8)     = r0;
        *(float4*)(out + (size_t)d * CC + lane * 8 + 4) = r1;
    }
}

// ---------------- host launch ----------------
extern "C" void kernel_launch(void* const* d_in, const int* in_sizes, int n_in,
                              void* d_out, int out_size) {
    const float* x      = (const float*)d_in[0];
    const void*  ei     = d_in[1];
    const float* W1     = (const float*)d_in[2];
    const float* a_src1 = (const float*)d_in[3];
    const float* a_dst1 = (const float*)d_in[4];
    const float* b1     = (const float*)d_in[5];
    const float* W2     = (const float*)d_in[6];
    const float* a_src2 = (const float*)d_in[7];
    const float* a_dst2 = (const float*)d_in[8];
    const float* b2     = (const float*)d_in[9];
    float* out = (float*)d_out;

    void* p_x2;
    cudaGetSymbolAddress(&p_x2, g_x2);
    float* x2 = (float*)p_x2;

    static cudaStream_t s2 = []{
        cudaStream_t t; cudaStreamCreateWithFlags(&t, cudaStreamNonBlocking); return t;
    }();
    static cudaEvent_t ev_fork = []{
        cudaEvent_t e; cudaEventCreateWithFlags(&e, cudaEventDisableTiming); return e;
    }();
    static cudaEvent_t ev_join = []{
        cudaEvent_t e; cudaEventCreateWithFlags(&e, cudaEventDisableTiming); return e;
    }();
    static cudaEvent_t ev_a0 = []{
        cudaEvent_t e; cudaEventCreateWithFlags(&e, cudaEventDisableTiming); return e;
    }();
    static cudaEvent_t ev_g0 = []{
        cudaEvent_t e; cudaEventCreateWithFlags(&e, cudaEventDisableTiming); return e;
    }();

    const int TB = 256;
    dim3 gemm_full((NN + 127) / 128, 4);
    dim3 gemm_h0(SPLIT / 128, 4);
    dim3 gemm_h1((NN - SPLIT + 127) / 128, 4);
    int agg_h0 = (SPLIT * 32) / TB;
    int agg_h1 = ((NN - SPLIT) * 32 + TB - 1) / TB;
    int agg_full = (NN * 32 + TB - 1) / TB;
    int edge_blocks = (ET + TB - 1) / TB;
    int node_blocks = (NN + TB - 1) / TB;

    // -------- fork: packed CSR on side stream, GEMM1 on main --------
    cudaEventRecord(ev_fork, 0);
    cudaStreamWaitEvent(s2, ev_fork, 0);

    init_kernel<<<node_blocks, TB, 0, s2>>>((const int*)ei);
    hist_kernel<<<edge_blocks, TB, 0, s2>>>(ei);
    assign_offsets_kernel<<<node_blocks, TB, 0, s2>>>();
    fill_kernel<<<edge_blocks, TB, 0, s2>>>(ei);
    cudaEventRecord(ev_join, s2);

    gemm_tc_kernel<128><<<gemm_full, TB>>>(x, W1, a_src1, a_dst1, 0);

    // -------- join; pipelined agg1 / GEMM2 --------
    cudaStreamWaitEvent(0, ev_join, 0);
    aggregate_kernel<1><<<agg_h0, TB>>>(x2, b1, 0, SPLIT);
    cudaEventRecord(ev_a0, 0);
    cudaStreamWaitEvent(s2, ev_a0, 0);
    gemm_tc_kernel<64><<<gemm_h0, TB, 0, s2>>>(x2, W2, a_src2, a_dst2, 0);
    cudaEventRecord(ev_g0, s2);

    aggregate_kernel<1><<<agg_h1, TB>>>(x2, b1, SPLIT, NN - SPLIT);
    gemm_tc_kernel<64><<<gemm_h1, TB>>>(x2, W2, a_src2, a_dst2, SPLIT);

    // -------- final aggregate (needs both GEMM2 halves) --------
    cudaStreamWaitEvent(0, ev_g0, 0);
    aggregate_kernel<0><<<agg_full, TB>>>(out, b2, 0, NN);
}

// round 16
// speedup vs baseline: 1.9657x; 1.0323x over previous
#include <cuda_runtime.h>
#include <cuda_fp16.h>

// ---------------- problem constants ----------------
#define NN    50000
#define EE    800000
#define ET    (EE + NN)      // edges + self loops = 850000
#define HC    256            // HEADS * 64
#define CC    64
#define NEG   0.2f
#define LOG2E 1.4426950408889634f
#define SPLIT 37632          // pipeline split point (multiple of 128)

typedef unsigned long long ull;

// ---------------- device scratch (static, no allocs) ----------------
__device__ __half g_hh [(size_t)NN * HC];  // hidden, fp16, [N,256]
__device__ float  g_as [NN * 4];           // alpha_src * log2e  [N,H]
__device__ float  g_ad [NN * 4];           // alpha_dst * log2e  [N,H]
__device__ float  g_x2 [(size_t)NN * CC];  // layer1 output (fp32)
__device__ int    g_srcs[ET];              // packed CSR: src per edge
__device__ int    g_cnt[NN];
__device__ int2   g_offcnt[NN];            // after fill: (end, count) per dst
__device__ int    g_total;
__device__ int    g_is64;

// ---------------- helpers ----------------
__device__ __forceinline__ void ffma2(ull& acc, ull a, ull b) {
    asm("fma.rn.f32x2 %0, %1, %2, %0;" : "+l"(acc) : "l"(a), "l"(b));
}
__device__ __forceinline__ ull pack2(float x, float y) {
    ull r;
    asm("mov.b64 %0, {%1, %2};" : "=l"(r) : "f"(x), "f"(y));
    return r;
}
__device__ __forceinline__ void unpack2(ull v, float& x, float& y) {
    asm("mov.b64 {%0, %1}, %2;" : "=f"(x), "=f"(y) : "l"(v));
}
__device__ __forceinline__ ull f2u(float2 v) { return pack2(v.x, v.y); }
__device__ __forceinline__ float ex2f(float x) {
    float r;
    asm("ex2.approx.f32 %0, %1;" : "=f"(r) : "f"(x));
    return r;
}

__device__ __forceinline__ void edge_sd(const void* ei, int e, int& s, int& d) {
    if (e < EE) {
        if (g_is64) {
            const long long* p = (const long long*)ei;
            s = (int)p[e]; d = (int)p[EE + e];
        } else {
            const int* p = (const int*)ei;
            s = p[e]; d = p[EE + e];
        }
    } else {
        s = d = e - EE;   // self loop
    }
}

// ---------------- fused init: zero counters + dtype detection ----------------
__global__ void init_kernel(const int* __restrict__ words) {
    int i = blockIdx.x * blockDim.x + threadIdx.x;
    if (i < NN) g_cnt[i] = 0;
    if (blockIdx.x == 0) {
        __shared__ int any;
        if (threadIdx.x == 0) { any = 0; g_total = 0; }
        __syncthreads();
        for (int j = threadIdx.x; j < 1024; j += blockDim.x)
            if (words[2 * j + 1] != 0) any = 1;
        __syncthreads();
        if (threadIdx.x == 0) g_is64 = any ? 0 : 1;
    }
}

// ---------------- CSR build (packed, order-free segments) ----------------
__global__ void hist_kernel(const void* __restrict__ ei) {
    int e = blockIdx.x * blockDim.x + threadIdx.x;
    if (e >= ET) return;
    int d;
    if (e < EE) {
        d = g_is64 ? ((const int*)ei)[2 * (EE + e)] : ((const int*)ei)[EE + e];
    } else {
        d = e - EE;
    }
    atomicAdd(&g_cnt[d], 1);
}

__global__ void assign_offsets_kernel() {
    int i = blockIdx.x * blockDim.x + threadIdx.x;
    if (i >= NN) return;
    int c = g_cnt[i];
    int o = atomicAdd(&g_total, c);
    g_offcnt[i] = make_int2(o, c);      // fill advances .x; ends at o + c
}

__global__ void fill_kernel(const void* __restrict__ ei) {
    int e = blockIdx.x * blockDim.x + threadIdx.x;
    if (e >= ET) return;
    int s, d; edge_sd(ei, e, s, d);
    int pos = atomicAdd(&g_offcnt[d].x, 1);
    g_srcs[pos] = s;
}

// ---------------- tensor-core GEMM (fp16 mma.sync, fp32 accum) ------------
__device__ __forceinline__ unsigned smem_u32(const void* p) {
    return (unsigned)__cvta_generic_to_shared(p);
}
__device__ __forceinline__ void ldmatrix_x4(unsigned& r0, unsigned& r1,
                                            unsigned& r2, unsigned& r3, unsigned addr) {
    asm volatile("ldmatrix.sync.aligned.m8n8.x4.shared.b16 {%0,%1,%2,%3}, [%4];"
                 : "=r"(r0), "=r"(r1), "=r"(r2), "=r"(r3) : "r"(addr));
}
__device__ __forceinline__ void ldmatrix_x2(unsigned& r0, unsigned& r1, unsigned addr) {
    asm volatile("ldmatrix.sync.aligned.m8n8.x2.shared.b16 {%0,%1}, [%2];"
                 : "=r"(r0), "=r"(r1) : "r"(addr));
}
__device__ __forceinline__ void mma16816(float* d, const unsigned* a, const unsigned* b) {
    asm volatile("mma.sync.aligned.m16n8k16.row.col.f32.f16.f16.f32 "
                 "{%0,%1,%2,%3}, {%4,%5,%6,%7}, {%8,%9}, {%0,%1,%2,%3};"
                 : "+f"(d[0]), "+f"(d[1]), "+f"(d[2]), "+f"(d[3])
                 : "r"(a[0]), "r"(a[1]), "r"(a[2]), "r"(a[3]), "r"(b[0]), "r"(b[1]));
}

#define ASTRIDE 40   // halfs per row; 80B row stride -> conflict-free ldmatrix

template <int K>
__global__ void __launch_bounds__(256)
gemm_tc_kernel(const float* __restrict__ X, const float* __restrict__ W,
               const float* __restrict__ a_src, const float* __restrict__ a_dst,
               int row0) {
    __shared__ __align__(16) __half As[128 * ASTRIDE];
    __shared__ __align__(16) __half Bs[64 * ASTRIDE];
    __shared__ float sred[2][128];
    __shared__ float dred[2][128];

    int tid = threadIdx.x;
    int lane = tid & 31, wid = tid >> 5;
    int wm = wid >> 1, wn = wid & 1;
    int bm = row0 + blockIdx.x * 128;
    int head = blockIdx.y;
    int bn = head * 64;

    float d[2][4][4];
    #pragma unroll
    for (int mt = 0; mt < 2; mt++)
        #pragma unroll
        for (int nt = 0; nt < 4; nt++)
            #pragma unroll
            for (int j = 0; j < 4; j++) d[mt][nt][j] = 0.f;

    for (int kt = 0; kt < K; kt += 32) {
        #pragma unroll
        for (int i = 0; i < 8; i++) {
            int lin = tid + i * 256;
            int r = lin >> 4, c2 = lin & 15;
            int row = bm + r;
            float2 v = make_float2(0.f, 0.f);
            if (row < NN) v = *(const float2*)&X[(size_t)row * K + kt + c2 * 2];
            *(__half2*)&As[r * ASTRIDE + c2 * 2] = __floats2half2_rn(v.x, v.y);
        }
        #pragma unroll
        for (int i = 0; i < 4; i++) {
            int lin = tid + i * 256;
            int r = lin >> 4, c2 = lin & 15;
            float2 v = *(const float2*)&W[(size_t)(bn + r) * K + kt + c2 * 2];
            *(__half2*)&Bs[r * ASTRIDE + c2 * 2] = __floats2half2_rn(v.x, v.y);
        }
        __syncthreads();

        #pragma unroll
        for (int kk = 0; kk < 32; kk += 16) {
            unsigned a[2][4], b[4][2];
            int l15 = lane & 15, lh = lane >> 4;
            #pragma unroll
            for (int mt = 0; mt < 2; mt++) {
                unsigned addr = smem_u32(&As[(wm * 32 + mt * 16 + l15) * ASTRIDE + kk + lh * 8]);
                ldmatrix_x4(a[mt][0], a[mt][1], a[mt][2], a[mt][3], addr);
            }
            int l7 = lane & 7, kh = (lane >> 3) & 1;
            #pragma unroll
            for (int nt = 0; nt < 4; nt++) {
                unsigned addr = smem_u32(&Bs[(wn * 32 + nt * 8 + l7) * ASTRIDE + kk + kh * 8]);
                ldmatrix_x2(b[nt][0], b[nt][1], addr);
            }
            #pragma unroll
            for (int mt = 0; mt < 2; mt++)
                #pragma unroll
                for (int nt = 0; nt < 4; nt++)
                    mma16816(d[mt][nt], a[mt], b[nt]);
        }
        __syncthreads();
    }

    // ---- epilogue: fp16 store + alpha partials (pre-scaled by log2e) ----
    int qrow = lane >> 2;
    int qcol = (lane & 3) * 2;
    float2 av[4], dv[4];
    #pragma unroll
    for (int nt = 0; nt < 4; nt++) {
        int c = wn * 32 + nt * 8 + qcol;
        av[nt] = *(const float2*)&a_src[bn + c];
        dv[nt] = *(const float2*)&a_dst[bn + c];
    }

    float sp[2][2] = {}, dp[2][2] = {};
    #pragma unroll
    for (int mt = 0; mt < 2; mt++) {
        int row = bm + wm * 32 + mt * 16 + qrow;
        #pragma unroll
        for (int nt = 0; nt < 4; nt++) {
            float d0 = d[mt][nt][0], d1 = d[mt][nt][1];
            float d2 = d[mt][nt][2], d3 = d[mt][nt][3];
            int col = bn + wn * 32 + nt * 8 + qcol;
            if (row < NN) {
                __half2 h = __floats2half2_rn(d0, d1);
                *(unsigned*)&g_hh[(size_t)row * HC + col] = *(unsigned*)&h;
            }
            if (row + 8 < NN) {
                __half2 h = __floats2half2_rn(d2, d3);
                *(unsigned*)&g_hh[(size_t)(row + 8) * HC + col] = *(unsigned*)&h;
            }
            sp[mt][0] += d0 * av[nt].x + d1 * av[nt].y;
            sp[mt][1] += d2 * av[nt].x + d3 * av[nt].y;
            dp[mt][0] += d0 * dv[nt].x + d1 * dv[nt].y;
            dp[mt][1] += d2 * dv[nt].x + d3 * dv[nt].y;
        }
    }
    #pragma unroll
    for (int mt = 0; mt < 2; mt++)
        #pragma unroll
        for (int h = 0; h < 2; h++) {
            sp[mt][h] += __shfl_xor_sync(0xFFFFFFFFu, sp[mt][h], 1);
            sp[mt][h] += __shfl_xor_sync(0xFFFFFFFFu, sp[mt][h], 2);
            dp[mt][h] += __shfl_xor_sync(0xFFFFFFFFu, dp[mt][h], 1);
            dp[mt][h] += __shfl_xor_sync(0xFFFFFFFFu, dp[mt][h], 2);
        }
    if ((lane & 3) == 0) {
        #pragma unroll
        for (int mt = 0; mt < 2; mt++) {
            int rl = wm * 32 + mt * 16 + qrow;
            sred[wn][rl]     = sp[mt][0];
            sred[wn][rl + 8] = sp[mt][1];
            dred[wn][rl]     = dp[mt][0];
            dred[wn][rl + 8] = dp[mt][1];
        }
    }
    __syncthreads();
    if (tid < 128) {
        int row = bm + tid;
        if (row < NN) {
            g_as[row * 4 + head] = (sred[0][tid] + sred[1][tid]) * LOG2E;
            g_ad[row * 4 + head] = (dred[0][tid] + dred[1][tid]) * LOG2E;
        }
    }
}

// ------- single-pass softmax + aggregate, f32x2 packed accumulation -------
// lane L: head = L>>3, cols = (L&7)*8-block of that head's 64.
// alphas pre-scaled by log2e; exp via ex2; offcnt.x holds segment END.
template <int ACT>
__global__ void __launch_bounds__(128, 10)
aggregate_kernel(float* __restrict__ out, const float* __restrict__ bias,
                 int dd0, int nd) {
    int d = dd0 + ((blockIdx.x * blockDim.x + threadIdx.x) >> 5);
    int lane = threadIdx.x & 31;
    if (d >= dd0 + nd) return;
    int2 oc = g_offcnt[d];
    int end = oc.x, beg = oc.x - oc.y;
    int hsel = lane >> 3;
    float adh = g_ad[d * 4 + hsel];

    float den = 0.f;
    ull a01 = 0ull, a23 = 0ull, a45 = 0ull, a67 = 0ull;

    int i = beg;
    for (; i + 3 < end; i += 4) {
        int   s[4];
        float a[4];
        uint4 u[4];
        #pragma unroll
        for (int j = 0; j < 4; j++) s[j] = g_srcs[i + j];
        #pragma unroll
        for (int j = 0; j < 4; j++) a[j] = g_as[s[j] * 4 + hsel];
        #pragma unroll
        for (int j = 0; j < 4; j++)
            u[j] = ((const uint4*)(g_hh + (size_t)s[j] * HC))[lane];
        #pragma unroll
        for (int j = 0; j < 4; j++) {
            float e = a[j] + adh;
            float ex = ex2f(fmaxf(e, NEG * e));
            den += ex;
            ull exd = pack2(ex, ex);
            ffma2(a01, f2u(__half22float2(*(const __half2*)&u[j].x)), exd);
            ffma2(a23, f2u(__half22float2(*(const __half2*)&u[j].y)), exd);
            ffma2(a45, f2u(__half22float2(*(const __half2*)&u[j].z)), exd);
            ffma2(a67, f2u(__half22float2(*(const __half2*)&u[j].w)), exd);
        }
    }
    for (; i < end; i++) {
        int s0 = g_srcs[i];
        float af = g_as[s0 * 4 + hsel];
        uint4 u0 = ((const uint4*)(g_hh + (size_t)s0 * HC))[lane];
        float e = af + adh;
        float ex = ex2f(fmaxf(e, NEG * e));
        den += ex;
        ull exd = pack2(ex, ex);
        ffma2(a01, f2u(__half22float2(*(const __half2*)&u0.x)), exd);
        ffma2(a23, f2u(__half22float2(*(const __half2*)&u0.y)), exd);
        ffma2(a45, f2u(__half22float2(*(const __half2*)&u0.z)), exd);
        ffma2(a67, f2u(__half22float2(*(const __half2*)&u0.w)), exd);
    }

    float acc[8];
    unpack2(a01, acc[0], acc[1]);
    unpack2(a23, acc[2], acc[3]);
    unpack2(a45, acc[4], acc[5]);
    unpack2(a67, acc[6], acc[7]);

    // normalize, then head-sum (lanes with same lane&7 hold the 4 heads)
    float wnorm = 0.25f / (den + 1e-16f);
    #pragma unroll
    for (int k = 0; k < 8; k++) {
        acc[k] *= wnorm;
        acc[k] += __shfl_xor_sync(0xFFFFFFFFu, acc[k], 8);
        acc[k] += __shfl_xor_sync(0xFFFFFFFFu, acc[k], 16);
    }

    if (lane < 8) {
        float4 b0 = *(const float4*)(bias + lane * 8);
        float4 b1 = *(const float4*)(bias + lane * 8 + 4);
        float4 r0, r1;
        r0.x = acc[0] + b0.x; r0.y = acc[1] + b0.y;
        r0.z = acc[2] + b0.z; r0.w = acc[3] + b0.w;
        r1.x = acc[4] + b1.x; r1.y = acc[5] + b1.y;
        r1.z = acc[6] + b1.z; r1.w = acc[7] + b1.w;
        if (ACT) {
            r0.x = r0.x > 0.f ? r0.x : expm1f(r0.x);
            r0.y = r0.y > 0.f ? r0.y : expm1f(r0.y);
            r0.z = r0.z > 0.f ? r0.z : expm1f(r0.z);
            r0.w = r0.w > 0.f ? r0.w : expm1f(r0.w);
            r1.x = r1.x > 0.f ? r1.x : expm1f(r1.x);
            r1.y = r1.y > 0.f ? r1.y : expm1f(r1.y);
            r1.z = r1.z > 0.f ? r1.z : expm1f(r1.z);
            r1.w = r1.w > 0.f ? r1.w : expm1f(r1.w);
        }
        *(float4*)(out + (size_t)d * CC + lane * 8)     = r0;
        *(float4*)(out + (size_t)d * CC + lane * 8 + 4) = r1;
    }
}

// ---------------- host launch ----------------
extern "C" void kernel_launch(void* const* d_in, const int* in_sizes, int n_in,
                              void* d_out, int out_size) {
    const float* x      = (const float*)d_in[0];
    const void*  ei     = d_in[1];
    const float* W1     = (const float*)d_in[2];
    const float* a_src1 = (const float*)d_in[3];
    const float* a_dst1 = (const float*)d_in[4];
    const float* b1     = (const float*)d_in[5];
    const float* W2     = (const float*)d_in[6];
    const float* a_src2 = (const float*)d_in[7];
    const float* a_dst2 = (const float*)d_in[8];
    const float* b2     = (const float*)d_in[9];
    float* out = (float*)d_out;

    void* p_x2;
    cudaGetSymbolAddress(&p_x2, g_x2);
    float* x2 = (float*)p_x2;

    static cudaStream_t s2 = []{
        cudaStream_t t; cudaStreamCreateWithFlags(&t, cudaStreamNonBlocking); return t;
    }();
    static cudaEvent_t ev_fork = []{
        cudaEvent_t e; cudaEventCreateWithFlags(&e, cudaEventDisableTiming); return e;
    }();
    static cudaEvent_t ev_join = []{
        cudaEvent_t e; cudaEventCreateWithFlags(&e, cudaEventDisableTiming); return e;
    }();
    static cudaEvent_t ev_a0 = []{
        cudaEvent_t e; cudaEventCreateWithFlags(&e, cudaEventDisableTiming); return e;
    }();
    static cudaEvent_t ev_g0 = []{
        cudaEvent_t e; cudaEventCreateWithFlags(&e, cudaEventDisableTiming); return e;
    }();

    const int TB = 256;
    const int AB = 128;                         // aggregate block size
    dim3 gemm_full((NN + 127) / 128, 4);
    dim3 gemm_h0(SPLIT / 128, 4);
    dim3 gemm_h1((NN - SPLIT + 127) / 128, 4);
    int agg_h0 = (SPLIT * 32) / AB;
    int agg_h1 = ((NN - SPLIT) * 32 + AB - 1) / AB;
    int agg_full = (NN * 32 + AB - 1) / AB;
    int edge_blocks = (ET + TB - 1) / TB;
    int node_blocks = (NN + TB - 1) / TB;

    // -------- fork: packed CSR on side stream, GEMM1 on main --------
    cudaEventRecord(ev_fork, 0);
    cudaStreamWaitEvent(s2, ev_fork, 0);

    init_kernel<<<node_blocks, TB, 0, s2>>>((const int*)ei);
    hist_kernel<<<edge_blocks, TB, 0, s2>>>(ei);
    assign_offsets_kernel<<<node_blocks, TB, 0, s2>>>();
    fill_kernel<<<edge_blocks, TB, 0, s2>>>(ei);
    cudaEventRecord(ev_join, s2);

    gemm_tc_kernel<128><<<gemm_full, TB>>>(x, W1, a_src1, a_dst1, 0);

    // -------- join; pipelined agg1 / GEMM2 --------
    cudaStreamWaitEvent(0, ev_join, 0);
    aggregate_kernel<1><<<agg_h0, AB>>>(x2, b1, 0, SPLIT);
    cudaEventRecord(ev_a0, 0);
    cudaStreamWaitEvent(s2, ev_a0, 0);
    gemm_tc_kernel<64><<<gemm_h0, TB, 0, s2>>>(x2, W2, a_src2, a_dst2, 0);
    cudaEventRecord(ev_g0, s2);

    aggregate_kernel<1><<<agg_h1, AB>>>(x2, b1, SPLIT, NN - SPLIT);
    gemm_tc_kernel<64><<<gemm_h1, TB>>>(x2, W2, a_src2, a_dst2, SPLIT);

    // -------- final aggregate (needs both GEMM2 halves) --------
    cudaStreamWaitEvent(0, ev_g0, 0);
    aggregate_kernel<0><<<agg_full, AB>>>(out, b2, 0, NN);
}